// round 3
// baseline (speedup 1.0000x reference)
#include <cuda_runtime.h>
#include <math.h>

#define D 256
#define O 10
#define NS 64
#define R 640   // NS*O

// ---------------- scratch ----------------
__device__ float d_H1[2 * NS * D];
__device__ float d_H2[2 * NS * D];
__device__ float d_G1[2 * R * D];  // rows s*10+a, s in 0..127 (batch1 then batch2)
__device__ float d_G2[2 * R * D];
__device__ float d_C[3][NS * NS];

// ================= K1: fused forward (both layers) + G2, 4 samples/CTA ===========
// grid 32, block 256. Thread t = output unit; 4 independent sample accumulators.
// x / h1 stored sample-transposed in smem -> one broadcast LDS.128 per K step.
__global__ __launch_bounds__(256) void k1_fwd(
    const float* __restrict__ x1, const float* __restrict__ x2,
    const float* __restrict__ W1, const float* __restrict__ b1,
    const float* __restrict__ W2, const float* __restrict__ b2,
    const float* __restrict__ W3)
{
    __shared__ __align__(16) float xT[D * 4];   // [i][s]
    __shared__ __align__(16) float h1T[D * 4];  // [i][s]

    const int t = threadIdx.x;
    const int s0 = blockIdx.x * 4;

    // load 4 sample rows, transpose into smem
#pragma unroll
    for (int s = 0; s < 4; s++) {
        int sg = s0 + s;
        const float* xr = (sg < NS) ? (x1 + sg * D) : (x2 + (sg - NS) * D);
        xT[t * 4 + s] = xr[t];
    }
    __syncthreads();

    // ---- layer 1 ----
    float bb = b1[t];
    float a0 = bb, a1 = bb, a2 = bb, a3 = bb;
#pragma unroll 8
    for (int i = 0; i < D; i++) {
        float w = W1[i * D + t];
        float4 xv = *(const float4*)&xT[i * 4];
        a0 += xv.x * w; a1 += xv.y * w; a2 += xv.z * w; a3 += xv.w * w;
    }
    float h10 = tanhf(a0), h11 = tanhf(a1), h12 = tanhf(a2), h13 = tanhf(a3);
    d_H1[(s0 + 0) * D + t] = h10;
    d_H1[(s0 + 1) * D + t] = h11;
    d_H1[(s0 + 2) * D + t] = h12;
    d_H1[(s0 + 3) * D + t] = h13;
    h1T[t * 4 + 0] = h10; h1T[t * 4 + 1] = h11;
    h1T[t * 4 + 2] = h12; h1T[t * 4 + 3] = h13;
    __syncthreads();

    // ---- layer 2 ----
    bb = b2[t];
    a0 = bb; a1 = bb; a2 = bb; a3 = bb;
#pragma unroll 8
    for (int i = 0; i < D; i++) {
        float w = W2[i * D + t];
        float4 hv = *(const float4*)&h1T[i * 4];
        a0 += hv.x * w; a1 += hv.y * w; a2 += hv.z * w; a3 += hv.w * w;
    }
    float h20 = tanhf(a0), h21 = tanhf(a1), h22 = tanhf(a2), h23 = tanhf(a3);
    d_H2[(s0 + 0) * D + t] = h20;
    d_H2[(s0 + 1) * D + t] = h21;
    d_H2[(s0 + 2) * D + t] = h22;
    d_H2[(s0 + 3) * D + t] = h23;
    float t20 = 1.f - h20 * h20, t21 = 1.f - h21 * h21;
    float t22 = 1.f - h22 * h22, t23 = 1.f - h23 * h23;

    // ---- G2[s,a,t] = W3[t,a] * (1 - h2^2) ----
#pragma unroll
    for (int a = 0; a < O; a++) {
        float w3 = W3[t * O + a];
        d_G2[((s0 + 0) * O + a) * D + t] = w3 * t20;
        d_G2[((s0 + 1) * O + a) * D + t] = w3 * t21;
        d_G2[((s0 + 2) * O + a) * D + t] = w3 * t22;
        d_G2[((s0 + 3) * O + a) * D + t] = w3 * t23;
    }
}

// ================= K_dots: C_l[n,m] = <feat_l(n), feat_l(m)> + 1 ==================
__global__ __launch_bounds__(256) void k_dots(
    const float* __restrict__ x1, const float* __restrict__ x2)
{
    __shared__ float xa[D], h1a[D], h2a[D];
    const int n = blockIdx.x;
    const int t = threadIdx.x;
    xa[t]  = x1[n * D + t];
    h1a[t] = d_H1[n * D + t];
    h2a[t] = d_H2[n * D + t];
    __syncthreads();

    const int warp = t >> 5, lane = t & 31;
#pragma unroll
    for (int mi = 0; mi < 8; mi++) {
        int m = warp * 8 + mi;
        const float* x2r = x2 + m * D;
        const float* h1r = d_H1 + (NS + m) * D;
        const float* h2r = d_H2 + (NS + m) * D;
        float s0 = 0.f, s1 = 0.f, s2 = 0.f;
#pragma unroll
        for (int k = lane; k < D; k += 32) {
            s0 += xa[k]  * x2r[k];
            s1 += h1a[k] * h1r[k];
            s2 += h2a[k] * h2r[k];
        }
#pragma unroll
        for (int off = 16; off > 0; off >>= 1) {
            s0 += __shfl_down_sync(0xffffffffu, s0, off);
            s1 += __shfl_down_sync(0xffffffffu, s1, off);
            s2 += __shfl_down_sync(0xffffffffu, s2, off);
        }
        if (lane == 0) {
            d_C[0][n * NS + m] = s0 + 1.0f;
            d_C[1][n * NS + m] = s1 + 1.0f;
            d_C[2][n * NS + m] = s2 + 1.0f;
        }
    }
}

// ================= K2: G1 = (G2 @ W2^T) .* (1-h1^2) — 32x32 NT-GEMM tiles =========
// grid (8, 40), 64 threads, 4x4 micro, K=256 in 8 register-pipelined stages.
__global__ __launch_bounds__(64) void k2_g1(const float* __restrict__ W2)
{
    __shared__ __align__(16) float As[32][36];
    __shared__ __align__(16) float Bs[32][36];

    const int tid = threadIdx.x;
    const int tx = tid & 7, ty = tid >> 3;
    const int r0 = blockIdx.y * 32;   // G2 row
    const int c0 = blockIdx.x * 32;   // output unit t

    float4 ra[4], rb[4];
    float acc[4][4] = {};

#define LDG_ST(kc) {                                                           \
    _Pragma("unroll")                                                          \
    for (int p = 0; p < 4; p++) {                                              \
        int slot = p * 64 + tid; int row = slot >> 3; int kq = slot & 7;       \
        ra[p] = *(const float4*)&d_G2[(r0 + row) * D + (kc) + kq * 4];         \
        rb[p] = *(const float4*)&W2[(c0 + row) * D + (kc) + kq * 4];           \
    } }
#define STS_ST() {                                                             \
    _Pragma("unroll")                                                          \
    for (int p = 0; p < 4; p++) {                                              \
        int slot = p * 64 + tid; int row = slot >> 3; int k0 = (slot & 7) * 4; \
        As[k0 + 0][row] = ra[p].x; As[k0 + 1][row] = ra[p].y;                  \
        As[k0 + 2][row] = ra[p].z; As[k0 + 3][row] = ra[p].w;                  \
        Bs[k0 + 0][row] = rb[p].x; Bs[k0 + 1][row] = rb[p].y;                  \
        Bs[k0 + 2][row] = rb[p].z; Bs[k0 + 3][row] = rb[p].w;                  \
    } }

    LDG_ST(0); STS_ST(); __syncthreads();
    for (int st = 0; st < 8; st++) {
        if (st < 7) LDG_ST((st + 1) * 32);
#pragma unroll
        for (int k = 0; k < 32; k++) {
            float4 a4 = *(const float4*)&As[k][ty * 4];
            float4 b4 = *(const float4*)&Bs[k][tx * 4];
            float av[4] = {a4.x, a4.y, a4.z, a4.w};
            float bv[4] = {b4.x, b4.y, b4.z, b4.w};
#pragma unroll
            for (int i = 0; i < 4; i++)
#pragma unroll
                for (int j = 0; j < 4; j++)
                    acc[i][j] += av[i] * bv[j];
        }
        if (st < 7) { __syncthreads(); STS_ST(); __syncthreads(); }
    }
#undef LDG_ST
#undef STS_ST

    // epilogue: scale by (1 - h1[s,t]^2), s = row/10
#pragma unroll
    for (int i = 0; i < 4; i++) {
        int r = r0 + ty * 4 + i;
        int s = r / 10;
        float4 hv = *(const float4*)&d_H1[s * D + c0 + tx * 4];
        float4 v;
        v.x = acc[i][0] * (1.f - hv.x * hv.x);
        v.y = acc[i][1] * (1.f - hv.y * hv.y);
        v.z = acc[i][2] * (1.f - hv.z * hv.z);
        v.w = acc[i][3] * (1.f - hv.w * hv.w);
        *(float4*)&d_G1[r * D + c0 + tx * 4] = v;
    }
}

// ================= K3: fused pair-GEMMs (both layers) + NTK combine ===============
__global__ __launch_bounds__(64) void k3_pair(float* __restrict__ out)
{
    __shared__ __align__(16) float As[32][36];
    __shared__ __align__(16) float Bs[32][36];

    const int tid = threadIdx.x;
    const int tx = tid & 7, ty = tid >> 3;
    const int r0 = blockIdx.y * 32, c0 = blockIdx.x * 32;

    float4 ra[4], rb[4];
    float acc0[4][4] = {};
    float acc1[4][4] = {};

#define LDG_STAGE(st) {                                                        \
    const float* G = ((st) < 8) ? d_G1 : d_G2;                                 \
    const int kc = ((st) & 7) * 32;                                            \
    const float* Ag = G + r0 * D + kc;                                         \
    const float* Bg = G + R * D + c0 * D + kc;                                 \
    _Pragma("unroll")                                                          \
    for (int p = 0; p < 4; p++) {                                              \
        int slot = p * 64 + tid; int row = slot >> 3; int kq = slot & 7;       \
        ra[p] = *(const float4*)&Ag[row * D + kq * 4];                         \
        rb[p] = *(const float4*)&Bg[row * D + kq * 4];                         \
    } }
#define STS_STAGE() {                                                          \
    _Pragma("unroll")                                                          \
    for (int p = 0; p < 4; p++) {                                              \
        int slot = p * 64 + tid; int row = slot >> 3; int k0 = (slot & 7) * 4; \
        As[k0 + 0][row] = ra[p].x; As[k0 + 1][row] = ra[p].y;                  \
        As[k0 + 2][row] = ra[p].z; As[k0 + 3][row] = ra[p].w;                  \
        Bs[k0 + 0][row] = rb[p].x; Bs[k0 + 1][row] = rb[p].y;                  \
        Bs[k0 + 2][row] = rb[p].z; Bs[k0 + 3][row] = rb[p].w;                  \
    } }
#define COMPUTE(ACC) {                                                         \
    _Pragma("unroll")                                                          \
    for (int k = 0; k < 32; k++) {                                             \
        float4 a4 = *(const float4*)&As[k][ty * 4];                            \
        float4 b4 = *(const float4*)&Bs[k][tx * 4];                            \
        float av[4] = {a4.x, a4.y, a4.z, a4.w};                                \
        float bv[4] = {b4.x, b4.y, b4.z, b4.w};                                \
        _Pragma("unroll")                                                      \
        for (int i = 0; i < 4; i++)                                            \
            _Pragma("unroll")                                                  \
            for (int j = 0; j < 4; j++)                                        \
                ACC[i][j] += av[i] * bv[j];                                    \
    } }

    LDG_STAGE(0); STS_STAGE(); __syncthreads();

    for (int st = 0; st < 8; st++) {
        LDG_STAGE(st + 1);
        COMPUTE(acc0);
        __syncthreads(); STS_STAGE(); __syncthreads();
    }
    for (int st = 8; st < 16; st++) {
        if (st < 15) LDG_STAGE(st + 1);
        COMPUTE(acc1);
        if (st < 15) { __syncthreads(); STS_STAGE(); __syncthreads(); }
    }

#pragma unroll
    for (int i = 0; i < 4; i++) {
        int row = r0 + ty * 4 + i;               // n*10 + a
        int n = row / 10, a = row - n * 10;
#pragma unroll
        for (int j = 0; j < 4; j++) {
            int col = c0 + tx * 4 + j;           // m*10 + b
            int m = col / 10, bb = col - m * 10;
            int ci = n * NS + m;
            float v = d_C[0][ci] * acc0[i][j] + d_C[1][ci] * acc1[i][j];
            if (a == bb) v += d_C[2][ci];
            out[(n * NS + m) * 100 + a * 10 + bb] = v;
        }
    }
#undef LDG_STAGE
#undef STS_STAGE
#undef COMPUTE
}

// ---------------- launcher ----------------
extern "C" void kernel_launch(void* const* d_in, const int* in_sizes, int n_in,
                              void* d_out, int out_size) {
    const float* x1 = (const float*)d_in[0];
    const float* x2 = (const float*)d_in[1];
    const float* W1 = (const float*)d_in[2];
    const float* b1 = (const float*)d_in[3];
    const float* W2 = (const float*)d_in[4];
    const float* b2 = (const float*)d_in[5];
    const float* W3 = (const float*)d_in[6];
    float* out = (float*)d_out;

    k1_fwd<<<32, 256>>>(x1, x2, W1, b1, W2, b2, W3);
    k_dots<<<64, 256>>>(x1, x2);
    k2_g1<<<dim3(8, 40), 64>>>(W2);
    k3_pair<<<dim3(20, 20), 64>>>(out);
}